// round 13
// baseline (speedup 1.0000x reference)
#include <cuda_runtime.h>
#include <cuda_bf16.h>

#define FULL 0xFFFFFFFFu
#define LOG2E 1.4426950408889634f

__device__ __forceinline__ float ex2f(float x) {
    float r; asm("ex2.approx.ftz.f32 %0, %1;" : "=f"(r) : "f"(x)); return r;
}

__device__ __forceinline__ float safe_neglog(float p) {
    // reference: where(p > THR, -log(max(p, THR)), 0); p > THR => max(p,THR)==p
    return (p > 9.2885e-30f) ? -__logf(p) : 0.0f;
}

// 2 rows per warp, segmented: lanes 0-15 own row0, lanes 16-31 own row1.
// Each lane holds 8 contiguous columns (2 float4 loads, coalesced across warp).
// __launch_bounds__(256, 6): 40-reg budget = exactly the 8x16B front-batched
// load destinations (32) + working set (8), at 6 blocks/SM residency.
__global__ __launch_bounds__(256, 6) void wmc_loss_kernel(
    const float4* __restrict__ s1g, const int4* __restrict__ y1g,
    const float4* __restrict__ s2g, const int4* __restrict__ y2g,
    float* __restrict__ out, int K)
{
    const int w    = (blockIdx.x * blockDim.x + threadIdx.x) >> 5;  // warp id
    const int lane = threadIdx.x & 31;
    const int seg  = lane >> 4;          // which row of the pair this lane owns
    const int sl   = lane & 15;          // lane within segment
    const int row0 = w * 2;
    if (row0 >= K) return;

    // pair spans 64 float4s; lane covers float4 idx {2*lane, 2*lane+1}
    // = row 'seg', columns sl*8 .. sl*8+7
    const long i0 = (long)row0 * 32 + lane * 2;
    const long i1 = i0 + 1;

    // ---- front-batched: 8 independent 16B streaming loads (MLP=8);
    //      Y first (consumed first) ----
    const int4   ya0 = __ldcs(y1g + i0), ya1 = __ldcs(y1g + i1);
    const int4   yb0 = __ldcs(y2g + i0), yb1 = __ldcs(y2g + i1);
    const float4 sa0 = __ldcs(s1g + i0), sa1 = __ldcs(s1g + i1);
    const float4 sb0 = __ldcs(s2g + i0), sb1 = __ldcs(s2g + i1);

    // ---- per-lane 8-bit occupancy masks over this lane's 8 columns ----
    unsigned m1 = 0, m2 = 0;
    m1 |= (unsigned)(ya0.x != 0) << 0; m2 |= (unsigned)(yb0.x != 0) << 0;
    m1 |= (unsigned)(ya0.y != 0) << 1; m2 |= (unsigned)(yb0.y != 0) << 1;
    m1 |= (unsigned)(ya0.z != 0) << 2; m2 |= (unsigned)(yb0.z != 0) << 2;
    m1 |= (unsigned)(ya0.w != 0) << 3; m2 |= (unsigned)(yb0.w != 0) << 3;
    m1 |= (unsigned)(ya1.x != 0) << 4; m2 |= (unsigned)(yb1.x != 0) << 4;
    m1 |= (unsigned)(ya1.y != 0) << 5; m2 |= (unsigned)(yb1.y != 0) << 5;
    m1 |= (unsigned)(ya1.z != 0) << 6; m2 |= (unsigned)(yb1.z != 0) << 6;
    m1 |= (unsigned)(ya1.w != 0) << 7; m2 |= (unsigned)(yb1.w != 0) << 7;

    // ---- 4 ballots: any(Y1), any(Y2), diff, multi-bit ----
    const unsigned sh = seg * 16;
    const unsigned balA1 = __ballot_sync(FULL, m1 != 0);
    const unsigned balA2 = __ballot_sync(FULL, m2 != 0);
    const unsigned balNE = __ballot_sync(FULL, m1 != m2);
    const unsigned balML = __ballot_sync(FULL, (m1 & (m1 - 1)) != 0);  // popc>=2

    const unsigned v1 = (balA1 >> sh) & 0xFFFFu;   // my row's lanes with Y1 bits
    const unsigned v2 = (balA2 >> sh) & 0xFFFFu;   // my row's lanes with Y2 bits
    const bool eq     = ((balNE >> sh) & 0xFFFFu) == 0;
    // s == 1  <=>  exactly one lane has bits, and no lane has >=2 bits
    const bool cse1 = eq && (__popc(v1) == 1) && (((balML >> sh) & 0xFFFFu) == 0);

    // a = first set col of Y1: la = first lane of segment with bits; ja = that
    // lane's first private bit. b = last set col of Y2, symmetric.
    const int la = (v1 ? (__ffs(v1) - 1) : 0) + seg * 16;
    const int lb = (v2 ? (31 - __clz(v2)) : 15) + seg * 16;
    const int f1 = __ffs(m1) - 1;           // -1 if none
    const int g2 = 31 - __clz(m2);          // -1 if none (clz(0)=32)
    const int ja = max(__shfl_sync(FULL, f1, la), 0);   // all-zero guard -> col 0
    const int jbv = __shfl_sync(FULL, g2, lb);
    const int jb = (jbv < 0) ? 7 : jbv;                 // all-zero guard -> col 127

    // ---- exp + partial sums with on-the-fly gather selection ----
    // No max-subtraction: scores are N(0,1) (|x| < ~6), fp32 exp2 range-safe.
    float A1[8] = {sa0.x, sa0.y, sa0.z, sa0.w, sa1.x, sa1.y, sa1.z, sa1.w};
    float A2[8] = {sb0.x, sb0.y, sb0.z, sb0.w, sb1.x, sb1.y, sb1.z, sb1.w};
    float z1 = 0.f, z2 = 0.f, cA1 = 0.f, cA2 = 0.f, cB1 = 0.f, cB2 = 0.f;
    #pragma unroll
    for (int jj = 0; jj < 8; jj++) {
        const float e1 = ex2f(A1[jj] * LOG2E); z1 += e1;
        const float e2 = ex2f(A2[jj] * LOG2E); z2 += e2;
        if (jj == ja) { cA1 = e1; cA2 = e2; }
        if (jj == jb) { cB1 = e1; cB2 = e2; }
    }

    // ---- segmented 4-level butterflies: both rows reduced in one chain ----
    #pragma unroll
    for (int o = 8; o; o >>= 1) {
        z1 += __shfl_xor_sync(FULL, z1, o);
        z2 += __shfl_xor_sync(FULL, z2, o);
    }
    const float inv1 = __frcp_rn(z1);
    const float inv2 = __frcp_rn(z2);

    // ---- per-segment gathers (per-lane source index is fine for SHFL.IDX) ----
    const float e1a = __shfl_sync(FULL, cA1, la);
    const float e2a = __shfl_sync(FULL, cA2, la);
    const float e1b = __shfl_sync(FULL, cB1, lb);
    const float e2b = __shfl_sync(FULL, cB2, lb);

    const float p1a = e1a * inv1, p2a = e2a * inv2;
    const float p1b = e1b * inv1, p2b = e2b * inv2;

    // case1 (equal one-hot):      -log p1a - log p2a
    // case2 + default (two distinct positions a,b):
    //      1 - (1 - P1[a]P2[b])(1 - P1[b]P2[a])
    float loss;
    if (cse1) {
        loss = safe_neglog(p1a) + safe_neglog(p2a);
    } else {
        const float prob = 1.f - (1.f - p1a * p2b) * (1.f - p1b * p2a);
        loss = safe_neglog(prob);
    }

    if (sl == 0 && (row0 + seg) < K) out[row0 + seg] = loss;
}

extern "C" void kernel_launch(void* const* d_in, const int* in_sizes, int n_in,
                              void* d_out, int out_size)
{
    const int K = in_sizes[0] / 128;          // rows; C = 128
    const int warps   = (K + 1) / 2;          // 2 rows per warp
    const int threads = 256;
    const int blocks  = (warps * 32 + threads - 1) / threads;
    wmc_loss_kernel<<<blocks, threads>>>(
        (const float4*)d_in[0], (const int4*)d_in[1],
        (const float4*)d_in[2], (const int4*)d_in[3],
        (float*)d_out, K);
}

// round 15
// speedup vs baseline: 1.0116x; 1.0116x over previous
#include <cuda_runtime.h>
#include <cuda_bf16.h>

#define FULL 0xFFFFFFFFu
#define LOG2E 1.4426950408889634f

__device__ __forceinline__ float ex2f(float x) {
    float r; asm("ex2.approx.ftz.f32 %0, %1;" : "=f"(r) : "f"(x)); return r;
}

__device__ __forceinline__ float safe_neglog(float p) {
    // reference: where(p > THR, -log(max(p, THR)), 0); p > THR => max(p,THR)==p
    return (p > 9.2885e-30f) ? -__logf(p) : 0.0f;
}

// 2 rows per warp, segmented: lanes 0-15 own row0, lanes 16-31 own row1.
// Each lane holds 8 contiguous columns (2 float4 loads, coalesced across warp).
__global__ __launch_bounds__(256) void wmc_loss_kernel(
    const float4* __restrict__ s1g, const int4* __restrict__ y1g,
    const float4* __restrict__ s2g, const int4* __restrict__ y2g,
    float* __restrict__ out, int K)
{
    const int w    = (blockIdx.x * blockDim.x + threadIdx.x) >> 5;  // warp id
    const int lane = threadIdx.x & 31;
    const int seg  = lane >> 4;          // which row of the pair this lane owns
    const int sl   = lane & 15;          // lane within segment
    const int row0 = w * 2;
    if (row0 >= K) return;

    // pair spans 64 float4s; lane covers float4 idx {2*lane, 2*lane+1}
    // = row 'seg', columns sl*8 .. sl*8+7
    const long i0 = (long)row0 * 32 + lane * 2;
    const long i1 = i0 + 1;

    // ---- front-batched: 8 independent 16B streaming loads;
    //      Y first (consumed first) ----
    const int4   ya0 = __ldcs(y1g + i0), ya1 = __ldcs(y1g + i1);
    const int4   yb0 = __ldcs(y2g + i0), yb1 = __ldcs(y2g + i1);
    const float4 sa0 = __ldcs(s1g + i0), sa1 = __ldcs(s1g + i1);
    const float4 sb0 = __ldcs(s2g + i0), sb1 = __ldcs(s2g + i1);

    int B1[8] = {ya0.x, ya0.y, ya0.z, ya0.w, ya1.x, ya1.y, ya1.z, ya1.w};
    int B2[8] = {yb0.x, yb0.y, yb0.z, yb0.w, yb1.x, yb1.y, yb1.z, yb1.w};

    // ---- per-lane 8-bit occupancy masks over this lane's 8 columns ----
    unsigned m1 = 0, m2 = 0;
    #pragma unroll
    for (int jj = 0; jj < 8; jj++) {
        m1 |= (unsigned)(B1[jj] != 0) << jj;
        m2 |= (unsigned)(B2[jj] != 0) << jj;
    }

    // ---- 4 ballots: any(Y1), any(Y2), diff, multi-bit ----
    const unsigned sh = seg * 16;
    const unsigned balA1 = __ballot_sync(FULL, m1 != 0);
    const unsigned balA2 = __ballot_sync(FULL, m2 != 0);
    const unsigned balNE = __ballot_sync(FULL, m1 != m2);
    const unsigned balML = __ballot_sync(FULL, (m1 & (m1 - 1)) != 0);  // popc>=2

    const unsigned v1 = (balA1 >> sh) & 0xFFFFu;   // my row's lanes with Y1 bits
    const unsigned v2 = (balA2 >> sh) & 0xFFFFu;   // my row's lanes with Y2 bits
    const bool eq     = ((balNE >> sh) & 0xFFFFu) == 0;
    // s == 1  <=>  exactly one lane has bits, and no lane has >=2 bits
    const bool cse1 = eq && (__popc(v1) == 1) && (((balML >> sh) & 0xFFFFu) == 0);

    // a = first set col of Y1: la = first lane of segment with bits; ja = that
    // lane's first private bit. b = last set col of Y2, symmetric.
    const int la = (v1 ? (__ffs(v1) - 1) : 0) + seg * 16;
    const int lb = (v2 ? (31 - __clz(v2)) : 15) + seg * 16;
    const int f1 = __ffs(m1) - 1;           // -1 if none
    const int g2 = 31 - __clz(m2);          // -1 if none (clz(0)=32)
    const int ja = max(__shfl_sync(FULL, f1, la), 0);   // all-zero guard -> col 0
    const int jbv = __shfl_sync(FULL, g2, lb);
    const int jb = (jbv < 0) ? 7 : jbv;                 // all-zero guard -> col 127

    // ---- exp + partial sums with on-the-fly gather selection ----
    // No max-subtraction: scores are N(0,1) (|x| < ~6), fp32 exp2 range-safe.
    float A1[8] = {sa0.x, sa0.y, sa0.z, sa0.w, sa1.x, sa1.y, sa1.z, sa1.w};
    float A2[8] = {sb0.x, sb0.y, sb0.z, sb0.w, sb1.x, sb1.y, sb1.z, sb1.w};
    float z1 = 0.f, z2 = 0.f, cA1 = 0.f, cA2 = 0.f, cB1 = 0.f, cB2 = 0.f;
    #pragma unroll
    for (int jj = 0; jj < 8; jj++) {
        const float e1 = ex2f(A1[jj] * LOG2E); z1 += e1;
        const float e2 = ex2f(A2[jj] * LOG2E); z2 += e2;
        if (jj == ja) { cA1 = e1; cA2 = e2; }
        if (jj == jb) { cB1 = e1; cB2 = e2; }
    }

    // ---- segmented 4-level butterflies: both rows reduced in one chain ----
    #pragma unroll
    for (int o = 8; o; o >>= 1) {
        z1 += __shfl_xor_sync(FULL, z1, o);
        z2 += __shfl_xor_sync(FULL, z2, o);
    }
    const float inv1 = __frcp_rn(z1);
    const float inv2 = __frcp_rn(z2);

    // ---- per-segment gathers (per-lane source index is fine for SHFL.IDX) ----
    const float e1a = __shfl_sync(FULL, cA1, la);
    const float e2a = __shfl_sync(FULL, cA2, la);
    const float e1b = __shfl_sync(FULL, cB1, lb);
    const float e2b = __shfl_sync(FULL, cB2, lb);

    const float p1a = e1a * inv1, p2a = e2a * inv2;
    const float p1b = e1b * inv1, p2b = e2b * inv2;

    // case1 (equal one-hot):      -log p1a - log p2a
    // case2 + default (two distinct positions a,b):
    //      1 - (1 - P1[a]P2[b])(1 - P1[b]P2[a])
    float loss;
    if (cse1) {
        loss = safe_neglog(p1a) + safe_neglog(p2a);
    } else {
        const float prob = 1.f - (1.f - p1a * p2b) * (1.f - p1b * p2a);
        loss = safe_neglog(prob);
    }

    if (sl == 0 && (row0 + seg) < K) out[row0 + seg] = loss;
}

extern "C" void kernel_launch(void* const* d_in, const int* in_sizes, int n_in,
                              void* d_out, int out_size)
{
    const int K = in_sizes[0] / 128;          // rows; C = 128
    const int warps   = (K + 1) / 2;          // 2 rows per warp
    const int threads = 256;
    const int blocks  = (warps * 32 + threads - 1) / threads;
    wmc_loss_kernel<<<blocks, threads>>>(
        (const float4*)d_in[0], (const int4*)d_in[1],
        (const float4*)d_in[2], (const int4*)d_in[3],
        (float*)d_out, K);
}